// round 14
// baseline (speedup 1.0000x reference)
#include <cuda_runtime.h>
#include <cuda_fp16.h>
#include <cstdint>

// ============================================================================
// Problem constants
// ============================================================================
#define BATCH   8
#define CDIM    512
#define HW      2304            // 48*48
#define TN      128             // query tile (N)
#define TM      128             // memory-row chunk (M)
#define NCHUNK  (HW / TM)       // 18
#define KC      64              // K per stage (fp16 elems)
#define KSTAGE  (CDIM / KC)     // 8
#define NSTAGES (NCHUNK * KSTAGE)   // 144 global stages per bank pair

// fp16 scratch (device globals: allocation-free rule)
__device__ __half g_bank_h[4][(size_t)BATCH * HW * CDIM];   // banks [B][HW][C]
__device__ __half g_kT[(size_t)BATCH * HW * CDIM];          // key^T [B][HW][C]

// ============================================================================
// Helpers (sm_80-level PTX only: compiles under compute_103)
// ============================================================================
__device__ __forceinline__ uint32_t smem_u32(const void* p) {
    uint32_t a;
    asm("{ .reg .u64 t; cvta.to.shared.u64 t, %1; cvt.u32.u64 %0, t; }"
        : "=r"(a) : "l"(p));
    return a;
}
__device__ __forceinline__ void cp_async16(uint32_t dst, const void* src) {
    asm volatile("cp.async.cg.shared.global [%0], [%1], 16;" :: "r"(dst), "l"(src));
}
__device__ __forceinline__ void prefetch_l2(const void* p) {
    asm volatile("prefetch.global.L2 [%0];" :: "l"(p));
}
#define CP_COMMIT() asm volatile("cp.async.commit_group;" ::: "memory")
#define CP_WAIT0()  asm volatile("cp.async.wait_group 0;" ::: "memory")
#define CP_WAIT1()  asm volatile("cp.async.wait_group 1;" ::: "memory")
// named barrier: 128-thread row-group rendezvous (ids 1..4)
__device__ __forceinline__ void bar_group(int id) {
    asm volatile("bar.sync %0, 128;" :: "r"(id) : "memory");
}

__device__ __forceinline__ void ldsm_x4(uint32_t& r0, uint32_t& r1,
                                        uint32_t& r2, uint32_t& r3, uint32_t a) {
    asm volatile("ldmatrix.sync.aligned.m8n8.x4.shared.b16 {%0,%1,%2,%3}, [%4];"
                 : "=r"(r0), "=r"(r1), "=r"(r2), "=r"(r3) : "r"(a));
}
__device__ __forceinline__ void mma16816(float* c, const uint32_t* a,
                                         uint32_t b0, uint32_t b1) {
    asm volatile(
        "mma.sync.aligned.m16n8k16.row.col.f32.f16.f16.f32 "
        "{%0,%1,%2,%3}, {%4,%5,%6,%7}, {%8,%9}, {%0,%1,%2,%3};"
        : "+f"(c[0]), "+f"(c[1]), "+f"(c[2]), "+f"(c[3])
        : "r"(a[0]), "r"(a[1]), "r"(a[2]), "r"(a[3]), "r"(b0), "r"(b1));
}

// ============================================================================
// SMEM layout: kT resident + 3-deep ring of A-tile pairs
// ============================================================================
static constexpr uint32_t SMEM_KT    = 0;
static constexpr uint32_t KT_BYTES   = TN * CDIM * 2;            // 131072
static constexpr uint32_t SMEM_A     = KT_BYTES;                 // 131072
static constexpr uint32_t A_BYTES    = TM * KC * 2;              // 16384 per bank
static constexpr uint32_t SMEM_TOTAL = SMEM_A + 6 * A_BYTES;     // 229376

// ============================================================================
// Preprocessing kernels
// ============================================================================
// fp32 -> fp16 bank conversion, 16 floats/thread via 4 independent grid-strided
// float4 chunks (MLP=4). __ldcs: inputs are single-use (evict-first).
__global__ void __launch_bounds__(256)
cvt2_kernel(const float* __restrict__ s0, const float* __restrict__ s1, int base) {
    const float* src = (blockIdx.y ? s1 : s0);
    __half* dst = g_bank_h[base + blockIdx.y];
    const size_t i0 = ((size_t)blockIdx.x * 256 + threadIdx.x) * 4;
    const size_t STRIDE = (size_t)2304 * 256 * 4;   // floats per chunk
    float4 v[4];
#pragma unroll
    for (int k = 0; k < 4; k++)
        v[k] = __ldcs((const float4*)(src + i0 + k * STRIDE));
#pragma unroll
    for (int k = 0; k < 4; k++) {
        __half2* d = (__half2*)(dst + i0 + k * STRIDE);
        d[0] = __floats2half2_rn(v[k].x, v[k].y);
        d[1] = __floats2half2_rn(v[k].z, v[k].w);
    }
}

__global__ void kt_kernel(const float* __restrict__ key) {
    __shared__ float t[32][33];
    int b  = blockIdx.z;
    int c0 = blockIdx.y * 32;
    int n0 = blockIdx.x * 32;
    int tx = threadIdx.x, ty = threadIdx.y;  // (32, 8)
#pragma unroll
    for (int i = 0; i < 4; i++) {
        int c = c0 + ty + i * 8;
        t[ty + i * 8][tx] = key[((size_t)b * CDIM + c) * HW + n0 + tx];
    }
    __syncthreads();
#pragma unroll
    for (int i = 0; i < 4; i++) {
        int n = n0 + ty + i * 8;
        g_kT[((size_t)b * HW + n) * CDIM + c0 + tx] = __float2half_rn(t[tx][ty + i * 8]);
    }
}

// ============================================================================
// Coarse scores (fp32 exact): channels 4..9  (side stream, hidden)
// ============================================================================
__global__ void __launch_bounds__(256)
coarse_kernel(const float* __restrict__ key,
              const float* __restrict__ b0, const float* __restrict__ b1,
              const float* __restrict__ b2, const float* __restrict__ b3,
              const float* __restrict__ b4, const float* __restrict__ b5,
              float* __restrict__ out) {
    __shared__ float cb[6][CDIM];
    __shared__ float red[8][6][32];
    const int b  = blockIdx.y;
    const int qt = threadIdx.x & 31;
    const int cg = threadIdx.x >> 5;            // 0..7 (64 C each)
    const int n  = blockIdx.x * 32 + qt;
    const float* banks[6] = {b0, b1, b2, b3, b4, b5};
    for (int o = 0; o < 6; o++)
        for (int i = threadIdx.x; i < CDIM; i += 256)
            cb[o][i] = banks[o][b * CDIM + i];
    __syncthreads();

    float acc[6] = {0.f, 0.f, 0.f, 0.f, 0.f, 0.f};
    const float* kp   = key + (size_t)b * CDIM * HW + (size_t)(cg * 64) * HW + n;
    const float* cbp0 = &cb[0][cg * 64];
    for (int c0 = 0; c0 < 64; c0 += 32) {
        float kv[32];
#pragma unroll
        for (int j = 0; j < 32; j++) kv[j] = kp[(size_t)(c0 + j) * HW];
#pragma unroll
        for (int j = 0; j < 32; j++) {
            float k = kv[j];
#pragma unroll
            for (int o = 0; o < 6; o++)
                acc[o] = fmaf(cbp0[o * CDIM + c0 + j], k, acc[o]);
        }
    }
#pragma unroll
    for (int o = 0; o < 6; o++) red[cg][o][qt] = acc[o];
    __syncthreads();
    if (threadIdx.x < 192) {
        int o = threadIdx.x >> 5, q = threadIdx.x & 31;
        float v = 0.f;
#pragma unroll
        for (int g = 0; g < 8; g++) v += red[g][o][q];
        out[((size_t)b * 10 + 4 + o) * HW + blockIdx.x * 32 + q] = v;
    }
}

// ============================================================================
// Main fused kernel: BOTH bank pairs in one launch, p = blockIdx.z.
// grid (18, 8, 2) = 288 CTAs -> HW wave-fills the tail of the P=0 wave with
// P=1 CTAs (no inter-kernel gap, no extra stream). 512 threads, R6 mainloop.
// ============================================================================
__global__ void __launch_bounds__(512, 1)
matcher_main(const float* __restrict__ sds, float* __restrict__ out) {
    extern __shared__ char smem[];
    const uint32_t sbase = smem_u32(smem);
    const int tid  = threadIdx.x;
    const int lane = tid & 31;
    const int warp = tid >> 5;
    const int warp_m = warp >> 2;           // 0..3: rows 32*warp_m (= tid>>7)
    const int warp_n = warp & 3;            // 0..3: cols 32*warp_n
    const int gtid = tid & 127;             // thread id within row-group
    const int bar_id = 1 + warp_m;          // named barrier per group
    const int b  = blockIdx.y;
    const int n0 = blockIdx.x * TN;
    const int p  = blockIdx.z;              // bank pair: 0 unmasked, 1 masked
    const float NEG_INF = __int_as_float(0xff800000);

    // ---- load resident kT tile [TN x CDIM] fp16, XOR-swizzled rows (1024B each)
    {
        const __half* src = g_kT + ((size_t)b * HW + n0) * CDIM;
#pragma unroll
        for (int i = 0; i < 16; i++) {
            int linear = i * 512 + tid;
            int n = linear >> 6;            // row (64x 16B units per row)
            int u = linear & 63;
            uint32_t dst = sbase + SMEM_KT + n * 1024 + ((u ^ (n & 7)) << 4);
            cp_async16(dst, src + (size_t)n * CDIM + u * 8);
        }
        CP_COMMIT();
        CP_WAIT0();
        __syncthreads();
    }

    // precomputed ldmatrix row geometry
    const int ia  = lane >> 3;              // 0..3 (x4 sub-matrix id)
    const int iah = ia >> 1;                // A: k-half within k16
    const int ib  = ia & 1;                 // B: k-half within k16
    int arow[2], brow4[2];
#pragma unroll
    for (int mf = 0; mf < 2; mf++)
        arow[mf] = warp_m * 32 + mf * 16 + ((ia & 1) << 3) + (lane & 7);
#pragma unroll
    for (int j2 = 0; j2 < 2; j2++)
        brow4[j2] = warp_n * 32 + j2 * 16 + ((lane >> 4) << 3) + (lane & 7);

    const int rrow    = lane >> 2;          // accum row-in-group
    const int ccol2   = (lane & 3) << 1;    // accum col pair base
    const int contrib = warp_m * 8 + rrow;

    const __half* bank0 = g_bank_h[2 * p + 0];
    const __half* bank1 = g_bank_h[2 * p + 1];

    float rmax[2][4][2];
#pragma unroll
    for (int u = 0; u < 2; u++)
#pragma unroll
        for (int j = 0; j < 4; j++)
            rmax[u][j][0] = rmax[u][j][1] = NEG_INF;

    float acc[2][2][4][4];

    // ---- prologue: group issues its rows for stages 0 and 1
#pragma unroll
    for (int g0 = 0; g0 < 2; g0++) {
        const int ck = g0 >> 3, s = g0 & 7, buf = g0 % 3;
#pragma unroll
        for (int u = 0; u < 2; u++) {
            const __half* src = (u ? bank1 : bank0)
                + ((size_t)b * HW + ck * TM + warp_m * 32) * CDIM + s * KC;
            uint32_t abase = sbase + SMEM_A + (buf * 2 + u) * A_BYTES
                           + warp_m * 32 * 128;
#pragma unroll
            for (int i = 0; i < 2; i++) {
                int linear = i * 128 + gtid;
                int m = linear >> 3, v = linear & 7;   // m: 0..31 local row
                int grow = warp_m * 32 + m;            // global row for swizzle
                cp_async16(abase + m * 128 + ((v ^ (grow & 7)) << 4),
                           src + (size_t)m * CDIM + v * 8);
            }
        }
        CP_COMMIT();
    }

    for (int g = 0; g < NSTAGES; g++) {
        const int chunk = g >> 3;
        const int s     = g & 7;
        const int m0    = chunk * TM;

        if (s == 0) {
#pragma unroll
            for (int u = 0; u < 2; u++)
#pragma unroll
                for (int mf = 0; mf < 2; mf++)
#pragma unroll
                    for (int j = 0; j < 4; j++)
#pragma unroll
                        for (int r = 0; r < 4; r++) acc[u][mf][j][r] = 0.f;
            if (p == 1) {
                // warm L2 for this chunk's mask block
                prefetch_l2(sds + ((size_t)b * HW + m0 + warp_m * 32 + lane) * HW
                            + n0 + warp_n * 32);
            }
        }

        // wait for stage g's group data, then group-local rendezvous
        if (g + 1 < NSTAGES) CP_WAIT1(); else CP_WAIT0();
        bar_group(bar_id);

        // group issues its rows for stage g+2 into ring buf (g+2)%3
        if (g + 2 < NSTAGES) {
            const int g2 = g + 2, ck = g2 >> 3, s2 = g2 & 7, buf = g2 % 3;
#pragma unroll
            for (int u = 0; u < 2; u++) {
                const __half* src = (u ? bank1 : bank0)
                    + ((size_t)b * HW + ck * TM + warp_m * 32) * CDIM + s2 * KC;
                uint32_t abase = sbase + SMEM_A + (buf * 2 + u) * A_BYTES
                               + warp_m * 32 * 128;
#pragma unroll
                for (int i = 0; i < 2; i++) {
                    int linear = i * 128 + gtid;
                    int m = linear >> 3, v = linear & 7;
                    int grow = warp_m * 32 + m;
                    cp_async16(abase + m * 128 + ((v ^ (grow & 7)) << 4),
                               src + (size_t)m * CDIM + v * 8);
                }
            }
            CP_COMMIT();
        }

        // ---- compute stage g from ring buf g%3
        const int buf = g % 3;
        const uint32_t a0 = sbase + SMEM_A + (buf * 2 + 0) * A_BYTES;
        const uint32_t a1 = sbase + SMEM_A + (buf * 2 + 1) * A_BYTES;
#pragma unroll
        for (int t = 0; t < 4; t++) {
            uint32_t bf[4][2];
            const int ku = ((s * 4 + t) << 1) + ib;
#pragma unroll
            for (int j2 = 0; j2 < 2; j2++)
                ldsm_x4(bf[2 * j2][0], bf[2 * j2][1],
                        bf[2 * j2 + 1][0], bf[2 * j2 + 1][1],
                        sbase + SMEM_KT + brow4[j2] * 1024
                        + ((ku ^ (brow4[j2] & 7)) << 4));
            uint32_t af[2][2][4];
#pragma unroll
            for (int mf = 0; mf < 2; mf++) {
                const int v = t * 2 + iah;
                const uint32_t off = arow[mf] * 128
                                   + ((v ^ (arow[mf] & 7)) << 4);
                ldsm_x4(af[0][mf][0], af[0][mf][1], af[0][mf][2], af[0][mf][3],
                        a0 + off);
                ldsm_x4(af[1][mf][0], af[1][mf][1], af[1][mf][2], af[1][mf][3],
                        a1 + off);
            }
#pragma unroll
            for (int u = 0; u < 2; u++)
#pragma unroll
                for (int mf = 0; mf < 2; mf++)
#pragma unroll
                    for (int j = 0; j < 4; j++)
                        mma16816(acc[u][mf][j], af[u][mf], bf[j][0], bf[j][1]);
        }

        // ---- end of chunk: fold max over its 128 memory rows
        if (s == 7) {
            if (p == 0) {
#pragma unroll
                for (int u = 0; u < 2; u++)
#pragma unroll
                    for (int j = 0; j < 4; j++) {
                        float m0v = rmax[u][j][0], m1v = rmax[u][j][1];
#pragma unroll
                        for (int mf = 0; mf < 2; mf++) {
                            m0v = fmaxf(m0v, fmaxf(acc[u][mf][j][0], acc[u][mf][j][2]));
                            m1v = fmaxf(m1v, fmaxf(acc[u][mf][j][1], acc[u][mf][j][3]));
                        }
                        rmax[u][j][0] = m0v; rmax[u][j][1] = m1v;
                    }
            } else {
#pragma unroll
                for (int mf = 0; mf < 2; mf++)
#pragma unroll
                    for (int h = 0; h < 2; h++) {
                        const int rg = m0 + warp_m * 32 + mf * 16 + h * 8 + rrow;
                        const float* mp = sds + ((size_t)b * HW + rg) * HW
                                        + n0 + warp_n * 32 + ccol2;
#pragma unroll
                        for (int j = 0; j < 4; j++) {
                            float2 mv = *(const float2*)(mp + j * 8);
#pragma unroll
                            for (int u = 0; u < 2; u++) {
                                rmax[u][j][0] = fmaxf(rmax[u][j][0],
                                                      acc[u][mf][j][h * 2 + 0] * mv.x);
                                rmax[u][j][1] = fmaxf(rmax[u][j][1],
                                                      acc[u][mf][j][h * 2 + 1] * mv.y);
                            }
                        }
                    }
            }
        }
    }

    // ---- cross-thread reduction via staging (reuses A-ring SMEM)
    __syncthreads();   // re-align ALL groups before SMEM reuse
    float* stg = (float*)(smem + SMEM_A);   // [2 banks][128 cols][32 contrib]
#pragma unroll
    for (int u = 0; u < 2; u++)
#pragma unroll
        for (int j = 0; j < 4; j++)
#pragma unroll
            for (int c = 0; c < 2; c++) {
                int col = warp_n * 32 + j * 8 + ccol2 + c;
                stg[(u * 128 + col) * 32 + contrib] = rmax[u][j][c];
            }
    __syncthreads();
    if (tid < 256) {
        int u = tid >> 7, col = tid & 127;
        float m = NEG_INF;
        const float* s = &stg[(u * 128 + col) * 32];
#pragma unroll
        for (int k = 0; k < 32; k++) m = fmaxf(m, s[k]);
        out[((size_t)b * 10 + p * 2 + u) * HW + n0 + col] = m;
    }
}

// ============================================================================
// Launch (4 streams total, same footprint as the passing R12 graph):
// cvt01 || cvt23 || kt || coarse up front, then ONE merged matcher launch.
// ============================================================================
extern "C" void kernel_launch(void* const* d_in, const int* in_sizes, int n_in,
                              void* d_out, int out_size) {
    (void)in_sizes; (void)n_in; (void)out_size;
    const float* key = (const float*)d_in[0];
    const float* sds = (const float*)d_in[1];
    float* out = (float*)d_out;

    static cudaStream_t s_coarse = nullptr, s_kt = nullptr, s_cvt = nullptr;
    static cudaEvent_t ev_fork = nullptr, ev_coarse = nullptr, ev_kt = nullptr;
    static cudaEvent_t ev_cvt23 = nullptr;
    if (s_coarse == nullptr) {
        cudaStreamCreateWithFlags(&s_coarse, cudaStreamNonBlocking);
        cudaStreamCreateWithFlags(&s_kt, cudaStreamNonBlocking);
        cudaStreamCreateWithFlags(&s_cvt, cudaStreamNonBlocking);
        cudaEventCreateWithFlags(&ev_fork, cudaEventDisableTiming);
        cudaEventCreateWithFlags(&ev_coarse, cudaEventDisableTiming);
        cudaEventCreateWithFlags(&ev_kt, cudaEventDisableTiming);
        cudaEventCreateWithFlags(&ev_cvt23, cudaEventDisableTiming);
        cudaFuncSetAttribute(matcher_main,
                             cudaFuncAttributeMaxDynamicSharedMemorySize, SMEM_TOTAL);
    }

    // fork
    cudaEventRecord(ev_fork, 0);
    cudaStreamWaitEvent(s_coarse, ev_fork, 0);
    cudaStreamWaitEvent(s_kt, ev_fork, 0);
    cudaStreamWaitEvent(s_cvt, ev_fork, 0);

    // side stream: coarse scores (channels 4..9) — fully independent
    coarse_kernel<<<dim3(HW / 32, BATCH), 256, 0, s_coarse>>>(key,
        (const float*)d_in[6], (const float*)d_in[7], (const float*)d_in[8],
        (const float*)d_in[9], (const float*)d_in[10], (const float*)d_in[11], out);

    // side stream: key transpose + fp16
    kt_kernel<<<dim3(HW / 32, CDIM / 32, BATCH), dim3(32, 8), 0, s_kt>>>(key);
    cudaEventRecord(ev_kt, s_kt);

    // main stream + cvt stream: convert all 4 banks concurrently (BW-bound)
    cvt2_kernel<<<dim3(2304, 2), 256>>>((const float*)d_in[2],
                                        (const float*)d_in[3], 0);
    cvt2_kernel<<<dim3(2304, 2), 256, 0, s_cvt>>>((const float*)d_in[4],
                                                  (const float*)d_in[5], 2);
    cudaEventRecord(ev_cvt23, s_cvt);

    // merged matcher: needs kt + all banks
    cudaStreamWaitEvent(0, ev_kt, 0);
    cudaStreamWaitEvent(0, ev_cvt23, 0);
    matcher_main<<<dim3(HW / TN, BATCH, 2), 512, SMEM_TOTAL>>>(sds, out);

    // join coarse before returning (it writes d_out)
    cudaEventRecord(ev_coarse, s_coarse);
    cudaStreamWaitEvent(0, ev_coarse, 0);
}

// round 15
// speedup vs baseline: 1.0283x; 1.0283x over previous
#include <cuda_runtime.h>
#include <cuda_fp16.h>
#include <cstdint>

// ============================================================================
// Problem constants
// ============================================================================
#define BATCH   8
#define CDIM    512
#define HW      2304            // 48*48
#define TN      128             // query tile (N)
#define TM      128             // memory-row chunk (M)
#define NCHUNK  (HW / TM)       // 18
#define KC      64              // K per stage (fp16 elems)
#define KSTAGE  (CDIM / KC)     // 8
#define NSTAGES (NCHUNK * KSTAGE)   // 144 global stages per bank pair

// fp16 scratch (device globals: allocation-free rule)
__device__ __half g_bank_h[4][(size_t)BATCH * HW * CDIM];   // banks [B][HW][C]
__device__ __half g_kT[(size_t)BATCH * HW * CDIM];          // key^T [B][HW][C]

// ============================================================================
// Helpers (sm_80-level PTX only: compiles under compute_103)
// ============================================================================
__device__ __forceinline__ uint32_t smem_u32(const void* p) {
    uint32_t a;
    asm("{ .reg .u64 t; cvta.to.shared.u64 t, %1; cvt.u32.u64 %0, t; }"
        : "=r"(a) : "l"(p));
    return a;
}
__device__ __forceinline__ void cp_async16(uint32_t dst, const void* src) {
    asm volatile("cp.async.cg.shared.global [%0], [%1], 16;" :: "r"(dst), "l"(src));
}
__device__ __forceinline__ void prefetch_l2(const void* p) {
    asm volatile("prefetch.global.L2 [%0];" :: "l"(p));
}
#define CP_COMMIT() asm volatile("cp.async.commit_group;" ::: "memory")
#define CP_WAIT0()  asm volatile("cp.async.wait_group 0;" ::: "memory")
#define CP_WAIT1()  asm volatile("cp.async.wait_group 1;" ::: "memory")
// named barrier: 128-thread row-group rendezvous (ids 1..4)
__device__ __forceinline__ void bar_group(int id) {
    asm volatile("bar.sync %0, 128;" :: "r"(id) : "memory");
}

__device__ __forceinline__ void ldsm_x4(uint32_t& r0, uint32_t& r1,
                                        uint32_t& r2, uint32_t& r3, uint32_t a) {
    asm volatile("ldmatrix.sync.aligned.m8n8.x4.shared.b16 {%0,%1,%2,%3}, [%4];"
                 : "=r"(r0), "=r"(r1), "=r"(r2), "=r"(r3) : "r"(a));
}
__device__ __forceinline__ void mma16816(float* c, const uint32_t* a,
                                         uint32_t b0, uint32_t b1) {
    asm volatile(
        "mma.sync.aligned.m16n8k16.row.col.f32.f16.f16.f32 "
        "{%0,%1,%2,%3}, {%4,%5,%6,%7}, {%8,%9}, {%0,%1,%2,%3};"
        : "+f"(c[0]), "+f"(c[1]), "+f"(c[2]), "+f"(c[3])
        : "r"(a[0]), "r"(a[1]), "r"(a[2]), "r"(a[3]), "r"(b0), "r"(b1));
}

// ============================================================================
// SMEM layout: kT resident + 3-deep ring of A-tile pairs
// ============================================================================
static constexpr uint32_t SMEM_KT    = 0;
static constexpr uint32_t KT_BYTES   = TN * CDIM * 2;            // 131072
static constexpr uint32_t SMEM_A     = KT_BYTES;                 // 131072
static constexpr uint32_t A_BYTES    = TM * KC * 2;              // 16384 per bank
static constexpr uint32_t SMEM_TOTAL = SMEM_A + 6 * A_BYTES;     // 229376

// ============================================================================
// Preprocessing kernels
// ============================================================================
// fp32 -> fp16 bank conversion, 16 floats/thread via 4 independent grid-strided
// float4 chunks (MLP=4). __ldcs: inputs are single-use (evict-first).
__global__ void __launch_bounds__(256)
cvt2_kernel(const float* __restrict__ s0, const float* __restrict__ s1, int base) {
    const float* src = (blockIdx.y ? s1 : s0);
    __half* dst = g_bank_h[base + blockIdx.y];
    const size_t i0 = ((size_t)blockIdx.x * 256 + threadIdx.x) * 4;
    const size_t STRIDE = (size_t)2304 * 256 * 4;   // floats per chunk
    float4 v[4];
#pragma unroll
    for (int k = 0; k < 4; k++)
        v[k] = __ldcs((const float4*)(src + i0 + k * STRIDE));
#pragma unroll
    for (int k = 0; k < 4; k++) {
        __half2* d = (__half2*)(dst + i0 + k * STRIDE);
        d[0] = __floats2half2_rn(v[k].x, v[k].y);
        d[1] = __floats2half2_rn(v[k].z, v[k].w);
    }
}

__global__ void kt_kernel(const float* __restrict__ key) {
    __shared__ float t[32][33];
    int b  = blockIdx.z;
    int c0 = blockIdx.y * 32;
    int n0 = blockIdx.x * 32;
    int tx = threadIdx.x, ty = threadIdx.y;  // (32, 8)
#pragma unroll
    for (int i = 0; i < 4; i++) {
        int c = c0 + ty + i * 8;
        t[ty + i * 8][tx] = key[((size_t)b * CDIM + c) * HW + n0 + tx];
    }
    __syncthreads();
#pragma unroll
    for (int i = 0; i < 4; i++) {
        int n = n0 + ty + i * 8;
        g_kT[((size_t)b * HW + n) * CDIM + c0 + tx] = __float2half_rn(t[tx][ty + i * 8]);
    }
}

// ============================================================================
// Coarse scores (fp32 exact): channels 4..9  (side stream, hidden)
// ============================================================================
__global__ void __launch_bounds__(256)
coarse_kernel(const float* __restrict__ key,
              const float* __restrict__ b0, const float* __restrict__ b1,
              const float* __restrict__ b2, const float* __restrict__ b3,
              const float* __restrict__ b4, const float* __restrict__ b5,
              float* __restrict__ out) {
    __shared__ float cb[6][CDIM];
    __shared__ float red[8][6][32];
    const int b  = blockIdx.y;
    const int qt = threadIdx.x & 31;
    const int cg = threadIdx.x >> 5;            // 0..7 (64 C each)
    const int n  = blockIdx.x * 32 + qt;
    const float* banks[6] = {b0, b1, b2, b3, b4, b5};
    for (int o = 0; o < 6; o++)
        for (int i = threadIdx.x; i < CDIM; i += 256)
            cb[o][i] = banks[o][b * CDIM + i];
    __syncthreads();

    float acc[6] = {0.f, 0.f, 0.f, 0.f, 0.f, 0.f};
    const float* kp   = key + (size_t)b * CDIM * HW + (size_t)(cg * 64) * HW + n;
    const float* cbp0 = &cb[0][cg * 64];
    for (int c0 = 0; c0 < 64; c0 += 32) {
        float kv[32];
#pragma unroll
        for (int j = 0; j < 32; j++) kv[j] = kp[(size_t)(c0 + j) * HW];
#pragma unroll
        for (int j = 0; j < 32; j++) {
            float k = kv[j];
#pragma unroll
            for (int o = 0; o < 6; o++)
                acc[o] = fmaf(cbp0[o * CDIM + c0 + j], k, acc[o]);
        }
    }
#pragma unroll
    for (int o = 0; o < 6; o++) red[cg][o][qt] = acc[o];
    __syncthreads();
    if (threadIdx.x < 192) {
        int o = threadIdx.x >> 5, q = threadIdx.x & 31;
        float v = 0.f;
#pragma unroll
        for (int g = 0; g < 8; g++) v += red[g][o][q];
        out[((size_t)b * 10 + 4 + o) * HW + blockIdx.x * 32 + q] = v;
    }
}

// ============================================================================
// Main fused kernel (one bank pair P): 2 GEMMs + (masked if P==1) max via
// HMMA m16n8k16. grid (18, 8), 512 threads (16 warps, 4x4), R6 mainloop:
// group-local pipelines, per-warp_m named barriers, 3-deep cp.async ring.
// ============================================================================
template <int P>
__global__ void __launch_bounds__(512, 1)
matcher_main(const float* __restrict__ sds, float* __restrict__ out) {
    extern __shared__ char smem[];
    const uint32_t sbase = smem_u32(smem);
    const int tid  = threadIdx.x;
    const int lane = tid & 31;
    const int warp = tid >> 5;
    const int warp_m = warp >> 2;           // 0..3: rows 32*warp_m (= tid>>7)
    const int warp_n = warp & 3;            // 0..3: cols 32*warp_n
    const int gtid = tid & 127;             // thread id within row-group
    const int bar_id = 1 + warp_m;          // named barrier per group
    const int b  = blockIdx.y;
    const int n0 = blockIdx.x * TN;
    const float NEG_INF = __int_as_float(0xff800000);

    // ---- load resident kT tile [TN x CDIM] fp16, XOR-swizzled rows (1024B each)
    {
        const __half* src = g_kT + ((size_t)b * HW + n0) * CDIM;
#pragma unroll
        for (int i = 0; i < 16; i++) {
            int linear = i * 512 + tid;
            int n = linear >> 6;            // row (64x 16B units per row)
            int u = linear & 63;
            uint32_t dst = sbase + SMEM_KT + n * 1024 + ((u ^ (n & 7)) << 4);
            cp_async16(dst, src + (size_t)n * CDIM + u * 8);
        }
        CP_COMMIT();
        CP_WAIT0();
        __syncthreads();
    }

    // precomputed ldmatrix row geometry
    const int ia  = lane >> 3;              // 0..3 (x4 sub-matrix id)
    const int iah = ia >> 1;                // A: k-half within k16
    const int ib  = ia & 1;                 // B: k-half within k16
    int arow[2], brow4[2];
#pragma unroll
    for (int mf = 0; mf < 2; mf++)
        arow[mf] = warp_m * 32 + mf * 16 + ((ia & 1) << 3) + (lane & 7);
#pragma unroll
    for (int j2 = 0; j2 < 2; j2++)
        brow4[j2] = warp_n * 32 + j2 * 16 + ((lane >> 4) << 3) + (lane & 7);

    const int rrow    = lane >> 2;          // accum row-in-group
    const int ccol2   = (lane & 3) << 1;    // accum col pair base
    const int contrib = warp_m * 8 + rrow;

    float rmax[2][4][2];
#pragma unroll
    for (int u = 0; u < 2; u++)
#pragma unroll
        for (int j = 0; j < 4; j++)
            rmax[u][j][0] = rmax[u][j][1] = NEG_INF;

    float acc[2][2][4][4];

    // ---- prologue: group issues its rows for stages 0 and 1
#pragma unroll
    for (int g0 = 0; g0 < 2; g0++) {
        const int ck = g0 >> 3, s = g0 & 7, buf = g0 % 3;
#pragma unroll
        for (int u = 0; u < 2; u++) {
            const __half* src = &g_bank_h[2 * P + u]
                [((size_t)b * HW + ck * TM + warp_m * 32) * CDIM + s * KC];
            uint32_t abase = sbase + SMEM_A + (buf * 2 + u) * A_BYTES
                           + warp_m * 32 * 128;
#pragma unroll
            for (int i = 0; i < 2; i++) {
                int linear = i * 128 + gtid;
                int m = linear >> 3, v = linear & 7;   // m: 0..31 local row
                int grow = warp_m * 32 + m;            // global row for swizzle
                cp_async16(abase + m * 128 + ((v ^ (grow & 7)) << 4),
                           src + (size_t)m * CDIM + v * 8);
            }
        }
        CP_COMMIT();
    }

    for (int g = 0; g < NSTAGES; g++) {
        const int chunk = g >> 3;
        const int s     = g & 7;
        const int m0    = chunk * TM;

        if (s == 0) {
#pragma unroll
            for (int u = 0; u < 2; u++)
#pragma unroll
                for (int mf = 0; mf < 2; mf++)
#pragma unroll
                    for (int j = 0; j < 4; j++)
#pragma unroll
                        for (int r = 0; r < 4; r++) acc[u][mf][j][r] = 0.f;
            if (P == 1) {
                // warm L2 for this chunk's mask block
                prefetch_l2(sds + ((size_t)b * HW + m0 + warp_m * 32 + lane) * HW
                            + n0 + warp_n * 32);
            }
        }

        // wait for stage g's group data, then group-local rendezvous
        if (g + 1 < NSTAGES) CP_WAIT1(); else CP_WAIT0();
        bar_group(bar_id);

        // group issues its rows for stage g+2 into ring buf (g+2)%3
        if (g + 2 < NSTAGES) {
            const int g2 = g + 2, ck = g2 >> 3, s2 = g2 & 7, buf = g2 % 3;
#pragma unroll
            for (int u = 0; u < 2; u++) {
                const __half* src = &g_bank_h[2 * P + u]
                    [((size_t)b * HW + ck * TM + warp_m * 32) * CDIM + s2 * KC];
                uint32_t abase = sbase + SMEM_A + (buf * 2 + u) * A_BYTES
                               + warp_m * 32 * 128;
#pragma unroll
                for (int i = 0; i < 2; i++) {
                    int linear = i * 128 + gtid;
                    int m = linear >> 3, v = linear & 7;
                    int grow = warp_m * 32 + m;
                    cp_async16(abase + m * 128 + ((v ^ (grow & 7)) << 4),
                               src + (size_t)m * CDIM + v * 8);
                }
            }
            CP_COMMIT();
        }

        // ---- compute stage g from ring buf g%3
        const int buf = g % 3;
        const uint32_t a0 = sbase + SMEM_A + (buf * 2 + 0) * A_BYTES;
        const uint32_t a1 = sbase + SMEM_A + (buf * 2 + 1) * A_BYTES;
#pragma unroll
        for (int t = 0; t < 4; t++) {
            uint32_t bf[4][2];
            const int ku = ((s * 4 + t) << 1) + ib;
#pragma unroll
            for (int j2 = 0; j2 < 2; j2++)
                ldsm_x4(bf[2 * j2][0], bf[2 * j2][1],
                        bf[2 * j2 + 1][0], bf[2 * j2 + 1][1],
                        sbase + SMEM_KT + brow4[j2] * 1024
                        + ((ku ^ (brow4[j2] & 7)) << 4));
            uint32_t af[2][2][4];
#pragma unroll
            for (int mf = 0; mf < 2; mf++) {
                const int v = t * 2 + iah;
                const uint32_t off = arow[mf] * 128
                                   + ((v ^ (arow[mf] & 7)) << 4);
                ldsm_x4(af[0][mf][0], af[0][mf][1], af[0][mf][2], af[0][mf][3],
                        a0 + off);
                ldsm_x4(af[1][mf][0], af[1][mf][1], af[1][mf][2], af[1][mf][3],
                        a1 + off);
            }
#pragma unroll
            for (int u = 0; u < 2; u++)
#pragma unroll
                for (int mf = 0; mf < 2; mf++)
#pragma unroll
                    for (int j = 0; j < 4; j++)
                        mma16816(acc[u][mf][j], af[u][mf], bf[j][0], bf[j][1]);
        }

        // ---- end of chunk: fold max over its 128 memory rows
        if (s == 7) {
            if (P == 0) {
#pragma unroll
                for (int u = 0; u < 2; u++)
#pragma unroll
                    for (int j = 0; j < 4; j++) {
                        float m0v = rmax[u][j][0], m1v = rmax[u][j][1];
#pragma unroll
                        for (int mf = 0; mf < 2; mf++) {
                            m0v = fmaxf(m0v, fmaxf(acc[u][mf][j][0], acc[u][mf][j][2]));
                            m1v = fmaxf(m1v, fmaxf(acc[u][mf][j][1], acc[u][mf][j][3]));
                        }
                        rmax[u][j][0] = m0v; rmax[u][j][1] = m1v;
                    }
            } else {
#pragma unroll
                for (int mf = 0; mf < 2; mf++)
#pragma unroll
                    for (int h = 0; h < 2; h++) {
                        const int rg = m0 + warp_m * 32 + mf * 16 + h * 8 + rrow;
                        const float* mp = sds + ((size_t)b * HW + rg) * HW
                                        + n0 + warp_n * 32 + ccol2;
#pragma unroll
                        for (int j = 0; j < 4; j++) {
                            float2 mv = *(const float2*)(mp + j * 8);
#pragma unroll
                            for (int u = 0; u < 2; u++) {
                                rmax[u][j][0] = fmaxf(rmax[u][j][0],
                                                      acc[u][mf][j][h * 2 + 0] * mv.x);
                                rmax[u][j][1] = fmaxf(rmax[u][j][1],
                                                      acc[u][mf][j][h * 2 + 1] * mv.y);
                            }
                        }
                    }
            }
        }
    }

    // ---- cross-thread reduction via staging (reuses A-ring SMEM)
    __syncthreads();   // re-align ALL groups before SMEM reuse
    float* stg = (float*)(smem + SMEM_A);   // [2 banks][128 cols][32 contrib]
#pragma unroll
    for (int u = 0; u < 2; u++)
#pragma unroll
        for (int j = 0; j < 4; j++)
#pragma unroll
            for (int c = 0; c < 2; c++) {
                int col = warp_n * 32 + j * 8 + ccol2 + c;
                stg[(u * 128 + col) * 32 + contrib] = rmax[u][j][c];
            }
    __syncthreads();
    if (tid < 256) {
        int u = tid >> 7, col = tid & 127;
        float m = NEG_INF;
        const float* s = &stg[(u * 128 + col) * 32];
#pragma unroll
        for (int k = 0; k < 32; k++) m = fmaxf(m, s[k]);
        out[((size_t)b * 10 + P * 2 + u) * HW + n0 + col] = m;
    }
}

// ============================================================================
// Launch: 4 streams (same count as the guard-passing R12 graph).
// matcher<1> rides the EXISTING s_cvt stream after cvt23 — it backfills
// matcher<0>'s retiring wave (R13's schedule, without the 5th stream).
// ============================================================================
extern "C" void kernel_launch(void* const* d_in, const int* in_sizes, int n_in,
                              void* d_out, int out_size) {
    (void)in_sizes; (void)n_in; (void)out_size;
    const float* key = (const float*)d_in[0];
    const float* sds = (const float*)d_in[1];
    float* out = (float*)d_out;

    static cudaStream_t s_coarse = nullptr, s_kt = nullptr, s_cvt = nullptr;
    static cudaEvent_t ev_fork = nullptr, ev_coarse = nullptr, ev_kt = nullptr;
    static cudaEvent_t ev_cvt01 = nullptr, ev_m1 = nullptr;
    if (s_coarse == nullptr) {
        cudaStreamCreateWithFlags(&s_coarse, cudaStreamNonBlocking);
        cudaStreamCreateWithFlags(&s_kt, cudaStreamNonBlocking);
        cudaStreamCreateWithFlags(&s_cvt, cudaStreamNonBlocking);
        cudaEventCreateWithFlags(&ev_fork, cudaEventDisableTiming);
        cudaEventCreateWithFlags(&ev_coarse, cudaEventDisableTiming);
        cudaEventCreateWithFlags(&ev_kt, cudaEventDisableTiming);
        cudaEventCreateWithFlags(&ev_cvt01, cudaEventDisableTiming);
        cudaEventCreateWithFlags(&ev_m1, cudaEventDisableTiming);
        cudaFuncSetAttribute(matcher_main<0>,
                             cudaFuncAttributeMaxDynamicSharedMemorySize, SMEM_TOTAL);
        cudaFuncSetAttribute(matcher_main<1>,
                             cudaFuncAttributeMaxDynamicSharedMemorySize, SMEM_TOTAL);
    }

    // fork
    cudaEventRecord(ev_fork, 0);
    cudaStreamWaitEvent(s_coarse, ev_fork, 0);
    cudaStreamWaitEvent(s_kt, ev_fork, 0);

    // side stream: coarse scores (channels 4..9) — fully independent
    coarse_kernel<<<dim3(HW / 32, BATCH), 256, 0, s_coarse>>>(key,
        (const float*)d_in[6], (const float*)d_in[7], (const float*)d_in[8],
        (const float*)d_in[9], (const float*)d_in[10], (const float*)d_in[11], out);

    // side stream: key transpose + fp16
    kt_kernel<<<dim3(HW / 32, CDIM / 32, BATCH), dim3(32, 8), 0, s_kt>>>(key);
    cudaEventRecord(ev_kt, s_kt);

    // main stream: convert banks 0,1 (critical path for matcher<0>)
    cvt2_kernel<<<dim3(2304, 2), 256>>>((const float*)d_in[2],
                                        (const float*)d_in[3], 0);
    cudaEventRecord(ev_cvt01, 0);

    // s_cvt: cvt23 after cvt01 (BW-serialized), then matcher<1> program-ordered
    cudaStreamWaitEvent(s_cvt, ev_cvt01, 0);
    cvt2_kernel<<<dim3(2304, 2), 256, 0, s_cvt>>>((const float*)d_in[4],
                                                  (const float*)d_in[5], 2);
    cudaStreamWaitEvent(s_cvt, ev_kt, 0);
    matcher_main<1><<<dim3(HW / TN, BATCH), 512, SMEM_TOTAL, s_cvt>>>(sds, out);
    cudaEventRecord(ev_m1, s_cvt);

    // main stream: matcher<0> after kt + cvt01 (program order)
    cudaStreamWaitEvent(0, ev_kt, 0);
    matcher_main<0><<<dim3(HW / TN, BATCH), 512, SMEM_TOTAL>>>(sds, out);

    // join matcher<1> + coarse before returning
    cudaStreamWaitEvent(0, ev_m1, 0);
    cudaEventRecord(ev_coarse, s_coarse);
    cudaStreamWaitEvent(0, ev_coarse, 0);
}